// round 5
// baseline (speedup 1.0000x reference)
#include <cuda_runtime.h>
#include <cuda_fp16.h>
#include <cstdint>

// Problem shape (fixed):
//   x      [2, 2048, 4096] fp32   -> M = 4096, K = 4096   (16,777,216 elems)
//   codes  [4096, 4096]    int32  -> N = 4096             (16,777,216 elems)
//   absmax [4096, 64]      fp32                           (   262,144 elems)
//   bias   [4096]          fp32                           (     4,096 elems)
//   out    [2, 2048, 4096] fp32 = [M, N] row-major

#define M_DIM 4096
#define N_DIM 4096
#define K_DIM 4096
#define BLOCKSIZE 64

// ---- static scratch (allocation-free rule: __device__ globals) ----
__device__ __half g_w[(size_t)N_DIM * K_DIM];   // dequantized weights, [n][k]
__device__ __half g_x[(size_t)M_DIM * K_DIM];   // fp16 activations,   [m][k]

__constant__ float c_nf4[16] = {
    -1.0f, -0.6961928009986877f, -0.5250730514526367f, -0.39491748809814453f,
    -0.28444138169288635f, -0.18477343022823334f, -0.09105003625154495f, 0.0f,
    0.07958029955625534f, 0.16093020141124725f, 0.24611230194568634f,
    0.33791524171829224f, 0.44070982933044434f, 0.5626170039176941f,
    0.6797559261322021f, 1.0f};

// ---------------------------------------------------------------------------
// Kernel 1 (fused prep): dequantize NF4 codes -> fp16 W, and x fp32 -> fp16.
// First NW blocks do W (N*K/4 vec4 items / 256), rest do x.
// ---------------------------------------------------------------------------
#define PREP_W_BLOCKS ((N_DIM * K_DIM / 4) / 256)
#define PREP_X_BLOCKS ((M_DIM * K_DIM / 4) / 256)

__global__ void __launch_bounds__(256) prep_kernel(
    const int* __restrict__ codes, const float* __restrict__ absmax,
    const float* __restrict__ x) {
    if (blockIdx.x < PREP_W_BLOCKS) {
        int i = blockIdx.x * 256 + threadIdx.x;         // vec-of-4 index
        int k4 = i & 1023;                              // K_DIM/4 = 1024
        int n  = i >> 10;
        int4 c = __ldg(((const int4*)codes) + i);
        float s = __ldg(absmax + n * (K_DIM / BLOCKSIZE) + (k4 >> 4));
        __half2 h0 = __floats2half2_rn(c_nf4[c.x] * s, c_nf4[c.y] * s);
        __half2 h1 = __floats2half2_rn(c_nf4[c.z] * s, c_nf4[c.w] * s);
        __half2* dst = (__half2*)g_w + (size_t)i * 2;
        dst[0] = h0;
        dst[1] = h1;
    } else {
        int i = (blockIdx.x - PREP_W_BLOCKS) * 256 + threadIdx.x;
        float4 v = __ldg(((const float4*)x) + i);
        __half2* dst = (__half2*)g_x + (size_t)i * 2;
        dst[0] = __floats2half2_rn(v.x, v.y);
        dst[1] = __floats2half2_rn(v.z, v.w);
    }
}

// ---------------------------------------------------------------------------
// Kernel 2: fp16 GEMM, fp32 accumulate, mma.sync.m16n8k16 + ldmatrix
// block tile 128x128x32, 8 warps (warp tile 64x32)
// 3-stage cp.async pipeline, ONE __syncthreads per k-iteration
// ---------------------------------------------------------------------------
#define BM 128
#define BN 128
#define BK 32
#define PAD 8            // row stride 40 halves = 80B -> conflict-free ldmatrix
#define STAGES 3
#define TILE_H (BM * (BK + PAD))              // halves per As (or Bs) stage
#define SMEM_BYTES (STAGES * 2 * TILE_H * 2)  // 61440

__device__ __forceinline__ void mma16816(float c[4], const uint32_t a[4],
                                         const uint32_t b[2]) {
    asm volatile(
        "mma.sync.aligned.m16n8k16.row.col.f32.f16.f16.f32 "
        "{%0,%1,%2,%3}, {%4,%5,%6,%7}, {%8,%9}, {%0,%1,%2,%3};\n"
        : "+f"(c[0]), "+f"(c[1]), "+f"(c[2]), "+f"(c[3])
        : "r"(a[0]), "r"(a[1]), "r"(a[2]), "r"(a[3]), "r"(b[0]), "r"(b[1]));
}

__device__ __forceinline__ void ldsm_x4(uint32_t r[4], uint32_t saddr) {
    asm volatile(
        "ldmatrix.sync.aligned.m8n8.x4.shared.b16 {%0,%1,%2,%3}, [%4];\n"
        : "=r"(r[0]), "=r"(r[1]), "=r"(r[2]), "=r"(r[3]) : "r"(saddr));
}

__device__ __forceinline__ void cp_async16(uint32_t smem_addr, const void* gptr) {
    asm volatile("cp.async.ca.shared.global [%0], [%1], 16;\n"
                 :: "r"(smem_addr), "l"(gptr));
}
__device__ __forceinline__ void cp_commit() {
    asm volatile("cp.async.commit_group;\n" ::: "memory");
}
template <int N>
__device__ __forceinline__ void cp_wait() {
    asm volatile("cp.async.wait_group %0;\n" :: "n"(N) : "memory");
}

__global__ void __launch_bounds__(256, 2) gemm_kernel(
    const float* __restrict__ bias, float* __restrict__ out) {
    extern __shared__ __half smem[];
    __half* As = smem;                    // STAGES tiles of BM x (BK+PAD)
    __half* Bs = smem + STAGES * TILE_H;  // STAGES tiles of BN x (BK+PAD)

    const int tid  = threadIdx.x;
    const int warp = tid >> 5;
    const int lane = tid & 31;
    const int g    = lane >> 2;   // 0..7
    const int tg   = lane & 3;    // 0..3

    const int wm = (warp & 1) * 64;
    const int wn = (warp >> 1) * 32;

    const int bm = blockIdx.y * BM;
    const int bn = blockIdx.x * BN;

    const __half* A = g_x;
    const __half* B = g_w;

    // gmem->smem: 512 16B-vectors per tile, 2 per thread
    const int r0 = tid >> 2;              // 0..63
    const int c0 = (tid & 3) * 8;

    // ldmatrix lane address: row = lane&15, k-half = (lane>>4)*8
    const int lrow  = lane & 15;
    const int lcolh = (lane >> 4) * 8;

    float acc[4][4][4];
    #pragma unroll
    for (int mt = 0; mt < 4; mt++)
        #pragma unroll
        for (int nt = 0; nt < 4; nt++)
            #pragma unroll
            for (int e = 0; e < 4; e++) acc[mt][nt][e] = 0.0f;

    auto load_tile = [&](int kt, int stage) {
        __half* as = As + stage * TILE_H;
        __half* bs = Bs + stage * TILE_H;
        #pragma unroll
        for (int i = 0; i < 2; i++) {
            int row = r0 + i * 64;
            cp_async16(
                (uint32_t)__cvta_generic_to_shared(&as[row * (BK + PAD) + c0]),
                &A[(size_t)(bm + row) * K_DIM + kt + c0]);
            cp_async16(
                (uint32_t)__cvta_generic_to_shared(&bs[row * (BK + PAD) + c0]),
                &B[(size_t)(bn + row) * K_DIM + kt + c0]);
        }
        cp_commit();
    };

    // prologue: prefetch tiles 0 and 1
    load_tile(0, 0);
    load_tile(BK, 1);

    const int NT = K_DIM / BK;           // 128
    for (int t = 0; t < NT; t++) {
        // tile t must be resident; tile t+1 may stay in flight
        if (t + 1 < NT) cp_wait<1>(); else cp_wait<0>();
        __syncthreads();
        // prefetch tile t+2 into stage (t+2)%3 = (t-1)%3; all its readers
        // (iteration t-1) passed the barrier above -> single-sync is safe
        if (t + 2 < NT) load_tile((t + 2) * BK, (t + 2) % STAGES);

        const __half* as = As + (t % STAGES) * TILE_H;
        const __half* bs = Bs + (t % STAGES) * TILE_H;

        #pragma unroll
        for (int ks = 0; ks < BK; ks += 16) {
            uint32_t a[4][4];
            uint32_t bf[2][4];
            #pragma unroll
            for (int mt = 0; mt < 4; mt++) {
                uint32_t sa = (uint32_t)__cvta_generic_to_shared(
                    &as[(wm + mt * 16 + lrow) * (BK + PAD) + ks + lcolh]);
                ldsm_x4(a[mt], sa);
            }
            #pragma unroll
            for (int p = 0; p < 2; p++) {
                uint32_t sb = (uint32_t)__cvta_generic_to_shared(
                    &bs[(wn + p * 16 + lrow) * (BK + PAD) + ks + lcolh]);
                ldsm_x4(bf[p], sb);
            }
            #pragma unroll
            for (int mt = 0; mt < 4; mt++) {
                #pragma unroll
                for (int nt = 0; nt < 4; nt++) {
                    int p = nt >> 1, h = nt & 1;
                    uint32_t b2[2] = {bf[p][h], bf[p][h + 2]};
                    mma16816(acc[mt][nt], a[mt], b2);
                }
            }
        }
    }

    // ---- epilogue: bias add + nonfinite clamp, STG.64 ----
    #pragma unroll
    for (int mt = 0; mt < 4; mt++) {
        #pragma unroll
        for (int nt = 0; nt < 4; nt++) {
            int r = bm + wm + mt * 16 + g;
            int c = bn + wn + nt * 8 + tg * 2;
            float b0 = __ldg(bias + c);
            float b1 = __ldg(bias + c + 1);
            float v0 = acc[mt][nt][0] + b0;
            float v1 = acc[mt][nt][1] + b1;
            float v2 = acc[mt][nt][2] + b0;
            float v3 = acc[mt][nt][3] + b1;
            if (!isfinite(v0)) v0 = 0.0f;
            if (!isfinite(v1)) v1 = 0.0f;
            if (!isfinite(v2)) v2 = 0.0f;
            if (!isfinite(v3)) v3 = 0.0f;
            *(float2*)&out[(size_t)r * N_DIM + c]       = make_float2(v0, v1);
            *(float2*)&out[(size_t)(r + 8) * N_DIM + c] = make_float2(v2, v3);
        }
    }
}

// ---------------------------------------------------------------------------
extern "C" void kernel_launch(void* const* d_in, const int* in_sizes, int n_in,
                              void* d_out, int out_size) {
    // Metadata order: x, codes, absmax, bias. x and codes have equal element
    // counts, so keep declared order for those; anchor the small tensors by
    // size as a safety net.
    const float* x      = (const float*)d_in[0];
    const int*   codes  = (const int*)d_in[1];
    const float* absmax = (const float*)d_in[2];
    const float* bias   = (const float*)d_in[3];
    for (int i = 2; i < n_in && i < 4; i++) {
        if (in_sizes[i] == N_DIM * (K_DIM / BLOCKSIZE))
            absmax = (const float*)d_in[i];
        else if (in_sizes[i] == N_DIM)
            bias = (const float*)d_in[i];
    }
    float* out = (float*)d_out;

    prep_kernel<<<PREP_W_BLOCKS + PREP_X_BLOCKS, 256>>>(codes, absmax, x);

    cudaFuncSetAttribute(gemm_kernel,
                         cudaFuncAttributeMaxDynamicSharedMemorySize,
                         SMEM_BYTES);
    dim3 grid(N_DIM / BN, M_DIM / BM);
    gemm_kernel<<<grid, 256, SMEM_BYTES>>>(bias, out);
}